// round 14
// baseline (speedup 1.0000x reference)
#include <cuda_runtime.h>
#include <cuda_fp16.h>
#include <math.h>

#define TT 4096
#define BB 32
#define NH 100
#define NM 65

// ---- scratch (__device__ globals: allocations forbidden) ----
__device__ __align__(16) float  g_nfac[TT*NM];
__device__ __align__(16) __half g_hmid[(size_t)BB*TT*NH];   // 26.2MB fp16 (sf, ratio deferred)
__device__ __align__(16) float  g_hmean[TT*NH];
__device__ float g_ratio[TT*BB];
__device__ float g_cmean[TT];
__device__ float g_sreso[TT];

__device__ __forceinline__ float wsum(float v){
  #pragma unroll
  for (int d=16; d; d>>=1) v += __shfl_xor_sync(0xffffffffu, v, d);
  return v;
}
// reduce to [-pi,pi] then MUFU sin; FMA keeps reduction error ~1e-5 @ 500 rad
__device__ __forceinline__ float fast_sin(float arg){
  float n = floorf(fmaf(arg, 0.15915494309f, 0.5f));
  float a = fmaf(n, -6.28318530718f, arg);
  return __sinf(a);
}

// ---- K1: per-t block. Phase1: pow+packed partials (full lanes). -----------
__global__ __launch_bounds__(512) void k_stats(const float* __restrict__ harm){
  int t = blockIdx.x;
  int tid = threadIdx.x;
  __shared__ float4 s_tfac4[25];
  __shared__ float4 s_sf4[32*26];   // [row][kq<25]
  __shared__ float4 s_prt[32*26];   // (lmax,num,den,-)
  __shared__ float  s_r[32];
  if (tid < NH+NM){
    // f32 phase recurrence tracked by double closed form (~1e-5 rad / 4096)
    const double INC  = (double)(float)1.0053096491487339;  // f32(2pi*40*64/16000)
    const double WRAP = (double)(float)6.283185307179586;   // f32(2pi)
    float phase = (float)fmod((double)(t+1)*INC, WRAP);
    if (tid < NH){
      float off = (float)((double)tid * (4.71238898038469/99.0));
      reinterpret_cast<float*>(s_tfac4)[tid] = 1.0f + 0.225f*fast_sin(phase + off);
    } else {
      int m = tid - NH;
      float rb = (float)m * 7.853981633974483f;             // f32(2.5pi)*m
      g_nfac[t*NM+m] = 1.0f + 0.6f*fast_sin(rb + phase);
    }
  }
  __syncthreads();
  const float4* hp = reinterpret_cast<const float4*>(harm);
  #pragma unroll
  for (int pass=0; pass<2; ++pass){
    int q = tid + pass*512;
    if (q < 800){
      int row = q/25, kq = q - row*25;
      float4 f = s_tfac4[kq];
      float4 x = hp[(size_t)row*(TT*25) + t*25 + kq];
      float4 sf;
      sf.x = __powf(x.x, 3.4f)*f.x;
      sf.y = __powf(x.y, 3.4f)*f.y;
      sf.z = __powf(x.z, 3.4f)*f.z;
      sf.w = __powf(x.w, 3.4f)*f.w;
      float lmax = fmaxf(fmaxf(x.x,x.y), fmaxf(x.z,x.w));
      float k0 = (float)(kq*4);
      float num = sf.x*k0 + sf.y*(k0+1.f) + sf.z*(k0+2.f) + sf.w*(k0+3.f);
      float den = sf.x+sf.y+sf.z+sf.w;
      s_sf4[row*26+kq] = sf;
      s_prt[row*26+kq] = make_float4(lmax, num, den, 0.f);
      __half2 p0 = __floats2half2_rn(sf.x, sf.y);
      __half2 p1 = __floats2half2_rn(sf.z, sf.w);
      uint2 pk;
      pk.x = *reinterpret_cast<unsigned int*>(&p0);
      pk.y = *reinterpret_cast<unsigned int*>(&p1);
      reinterpret_cast<uint2*>(g_hmid + ((size_t)row*TT + t)*NH)[kq] = pk;
    }
  }
  __syncthreads();
  if (tid < 32){
    int row = tid;
    float mo = 0.f, num = 0.f, den = 0.f;
    #pragma unroll
    for (int l=0;l<25;++l){
      float4 p = s_prt[row*26+l];
      mo = fmaxf(mo, p.x); num += p.y; den += p.z;
    }
    mo = fmaxf(mo, 1e-6f);
    float ms = fmaxf(__powf(mo, 3.4f), 1e-6f);
    float ratio = __fdividef(mo, ms);
    float cen = __fdividef(num, fmaxf(den, 1e-6f));  // ratio cancels in quotient
    s_r[row] = ratio;
    g_ratio[t*32+row] = ratio;
    float cs = wsum(cen);
    if (row == 0) g_cmean[t] = cs * (1.f/32.f);
  }
  __syncthreads();
  if (tid < NH){
    const float* sfp = reinterpret_cast<const float*>(s_sf4);
    float sum = 0.f;
    #pragma unroll
    for (int b=0;b<32;++b) sum = fmaf(s_r[b], sfp[b*104+tid], sum);
    g_hmean[t*NH+tid] = sum * (1.f/32.f);
  }
}

// ---- K2: fb affine scan + clock prefix sum (256 thr x 16 elems, double) ---
__global__ void k_scan(){
  __shared__ double s_clk[TT];
  __shared__ double s_wa[8], s_wb[8], s_ws[8];
  int tid = threadIdx.x;
  int lane = tid & 31, warp = tid >> 5;
  int base = tid * 16;
  const double RATE_K = 0.725 * 6.283185307179586 * 0.004;
  double v = 0.0;
  #pragma unroll
  for (int j=0;j<16;++j){
    double u = 0.1*(((double)g_cmean[base+j] - 30.0)/40.0);
    v = 0.9*v + u;
  }
  double a = 0.18530201888518416;  // 0.9^16
  double b = v;
  #pragma unroll
  for (int d=1; d<32; d<<=1){
    double pa = __shfl_up_sync(0xffffffffu, a, d);
    double pb = __shfl_up_sync(0xffffffffu, b, d);
    if (lane >= d){ b = a*pb + b; a = a*pa; }
  }
  if (lane == 31){ s_wa[warp]=a; s_wb[warp]=b; }
  __syncthreads();
  double wpre = 0.0;
  for (int w=0; w<warp; ++w) wpre = s_wa[w]*wpre + s_wb[w];
  double ae = __shfl_up_sync(0xffffffffu, a, 1);
  double be = __shfl_up_sync(0xffffffffu, b, 1);
  double fb = (lane==0) ? wpre : (ae*wpre + be);
  double csum = 0.0;
  #pragma unroll
  for (int j=0;j<16;++j){
    double u = 0.1*(((double)g_cmean[base+j] - 30.0)/40.0);
    fb = 0.9*fb + u;
    csum += RATE_K * (1.0 + 0.4*fb);
    s_clk[base+j] = csum;
  }
  double S = csum, ss = S;
  #pragma unroll
  for (int d=1; d<32; d<<=1){
    double p = __shfl_up_sync(0xffffffffu, ss, d);
    if (lane >= d) ss += p;
  }
  if (lane == 31) s_ws[warp] = ss;
  __syncthreads();
  double off = 0.0;
  for (int w=0; w<warp; ++w) off += s_ws[w];
  double excl = off + ss - S;
  #pragma unroll
  for (int j=0;j<16;++j){
    double c = fmod(excl + s_clk[base+j], 6.283185307179586);
    g_sreso[base+j] = 0.4f * sinf((float)c);
  }
}

// ---- K3: h epilogue, 800 thr = 32 rows x 25 quads, no loop/div; noise -----
__global__ __launch_bounds__(800) void k_out(const float4* __restrict__ nin,
                                             float4* __restrict__ outh,
                                             float4* __restrict__ outn){
  int bid = blockIdx.x;
  int tid = threadIdx.x;
  if (bid >= TT){
    const int NVN = BB*TT*NM/4;
    const int M = TT*NM/4;
    int nb = gridDim.x - TT;
    int stride = nb*800;
    int j = (bid - TT)*800 + tid;
    int fi = j % M;
    int sm = stride % M;
    for (; j < NVN; j += stride){
      float4 v = nin[j];
      float4 f = reinterpret_cast<const float4*>(g_nfac)[fi];
      v.x *= f.x; v.y *= f.y; v.z *= f.z; v.w *= f.w;
      outn[j] = v;
      fi += sm; if (fi >= M) fi -= M;
    }
    return;
  }
  int t = bid;
  __shared__ float4 s_a[25], s_c[25];
  __shared__ float  s_r2[32];
  if (tid < 32) s_r2[tid] = g_ratio[t*32+tid];
  if (tid < 25){
    float sr = g_sreso[t];
    int k4 = tid*4;
    float4 rel;
    rel.x = (float)k4/99.0f*2.0f - 1.0f;
    rel.y = (float)(k4+1)/99.0f*2.0f - 1.0f;
    rel.z = (float)(k4+2)/99.0f*2.0f - 1.0f;
    rel.w = (float)(k4+3)/99.0f*2.0f - 1.0f;
    float scale = (t==0) ? 1.0f : 0.6f;
    float4 a;
    a.x = scale*(1.0f + sr*rel.x); a.y = scale*(1.0f + sr*rel.y);
    a.z = scale*(1.0f + sr*rel.z); a.w = scale*(1.0f + sr*rel.w);
    float4 c = make_float4(0.f,0.f,0.f,0.f);
    if (t >= 149){
      float srp = g_sreso[t-149];
      float4 hm = reinterpret_cast<const float4*>(g_hmean)[(t-149)*25 + tid];
      c.x = 0.4f*(1.0f + srp*rel.x)*hm.x;
      c.y = 0.4f*(1.0f + srp*rel.y)*hm.y;
      c.z = 0.4f*(1.0f + srp*rel.z)*hm.z;
      c.w = 0.4f*(1.0f + srp*rel.w)*hm.w;
    }
    s_a[tid] = a; s_c[tid] = c;
  }
  __syncthreads();
  int row = tid/25, kq = tid - row*25;
  float r = s_r2[row];
  uint2 pk = reinterpret_cast<const uint2*>(g_hmid + ((size_t)row*TT + t)*NH)[kq];
  __half2 p0 = *reinterpret_cast<__half2*>(&pk.x);
  __half2 p1 = *reinterpret_cast<__half2*>(&pk.y);
  float2 v01 = __half22float2(p0);
  float2 v23 = __half22float2(p1);
  float4 a = s_a[kq], c = s_c[kq];
  float4 o;
  o.x = fmaf(a.x, r*v01.x, c.x); o.y = fmaf(a.y, r*v01.y, c.y);
  o.z = fmaf(a.z, r*v23.x, c.z); o.w = fmaf(a.w, r*v23.y, c.w);
  outh[((size_t)row*TT + t)*25 + kq] = o;
}

extern "C" void kernel_launch(void* const* d_in, const int* in_sizes, int n_in,
                              void* d_out, int out_size){
  const float* harm  = (const float*)d_in[0];
  const float* noise = (const float*)d_in[1];
  float* outh = (float*)d_out;
  float* outn = outh + (size_t)BB*TT*NH;
  k_stats<<<TT, 512>>>(harm);
  k_scan <<<1, 256>>>();
  k_out  <<<TT + 1024, 800>>>((const float4*)noise, (float4*)outh, (float4*)outn);
}

// round 15
// speedup vs baseline: 1.2998x; 1.2998x over previous
#include <cuda_runtime.h>
#include <cuda_fp16.h>
#include <math.h>

#define TT 4096
#define BB 32
#define NH 100
#define NM 65
#define PADK 104   // float stride for sf rows (104%32=8, consecutive-tid reads conflict-free)
#define PADP 27    // float4 stride for partials (108 words; 12 mod 32 -> conflict-free)

// ---- scratch (__device__ globals: allocations forbidden) ----
__device__ __align__(16) float  g_nfac[TT*NM];
__device__ __align__(16) __half g_hmid[(size_t)BB*TT*NH];   // 26.2MB fp16 (sf, ratio deferred)
__device__ __align__(16) float  g_hmean[TT*NH];
__device__ float g_ratio[TT*BB];
__device__ float g_cmean[TT];
__device__ float g_sreso[TT];

__device__ __forceinline__ float wsum(float v){
  #pragma unroll
  for (int d=16; d; d>>=1) v += __shfl_xor_sync(0xffffffffu, v, d);
  return v;
}
// reduce to [-pi,pi] then MUFU sin; error ~1e-5 rad at |arg|<=600
__device__ __forceinline__ float fast_sin(float arg){
  float n = floorf(fmaf(arg, 0.15915494309f, 0.5f));
  float a = fmaf(n, -6.28318530718f, arg);
  return __sinf(a);
}

// ---- K1: per-t block. Phase1: pow+partials. Phase2: per-row + column sums. -
__global__ __launch_bounds__(512) void k_stats(const float* __restrict__ harm){
  int t = blockIdx.x;
  int warp = threadIdx.x>>5, lane = threadIdx.x&31;
  int tid = threadIdx.x;
  __shared__ float  s_tfac[NH];
  __shared__ float  s_sf[32*PADK];     // fp32 sf per row
  __shared__ float4 s_prt[32*PADP];    // (lmax,num,den,-) per row x lane
  __shared__ float  s_r[32];
  if (tid < NH+NM){
    // f32 phase recurrence tracked by double closed form (~1e-5 rad / 4096)
    const double INC  = (double)(float)1.0053096491487339;  // f32(2pi*40*64/16000)
    const double WRAP = (double)(float)6.283185307179586;   // f32(2pi)
    float phase = (float)fmod((double)(t+1)*INC, WRAP);
    if (tid < NH){
      float off = (float)((double)tid * (4.71238898038469/99.0));
      s_tfac[tid] = 1.0f + 0.225f*fast_sin(phase + off);
    } else {
      int m = tid - NH;
      float rb = (float)m * 7.853981633974483f;             // f32(2.5pi)*m
      g_nfac[t*NM+m] = 1.0f + 0.6f*fast_sin(rb + phase);
    }
  }
  __syncthreads();
  bool act = lane < 25;
  float4 f = act ? reinterpret_cast<const float4*>(s_tfac)[lane]
                 : make_float4(0.f,0.f,0.f,0.f);
  float k0 = (float)(lane*4);
  #pragma unroll
  for (int r=0;r<2;++r){
    int b = warp + r*16;                      // row 0..31
    size_t rowoff = ((size_t)b*TT + t)*NH;
    float4 x = act ? reinterpret_cast<const float4*>(harm + rowoff)[lane]
                   : make_float4(0.f,0.f,0.f,0.f);
    // pow without clamp: x>=0; x<1e-6 diff <= 9e-21 abs (negligible)
    float4 sf;
    sf.x = __powf(x.x, 3.4f)*f.x;
    sf.y = __powf(x.y, 3.4f)*f.y;
    sf.z = __powf(x.z, 3.4f)*f.z;
    sf.w = __powf(x.w, 3.4f)*f.w;
    float lmax = fmaxf(fmaxf(x.x,x.y), fmaxf(x.z,x.w));
    float num = sf.x*k0 + sf.y*(k0+1.f) + sf.z*(k0+2.f) + sf.w*(k0+3.f);
    float den = sf.x+sf.y+sf.z+sf.w;
    if (act){
      reinterpret_cast<float4*>(s_sf + b*PADK)[lane] = sf;
      s_prt[b*PADP+lane] = make_float4(lmax, num, den, 0.f);
      __half2 p0 = __floats2half2_rn(sf.x, sf.y);
      __half2 p1 = __floats2half2_rn(sf.z, sf.w);
      uint2 pk;
      pk.x = *reinterpret_cast<unsigned int*>(&p0);
      pk.y = *reinterpret_cast<unsigned int*>(&p1);
      reinterpret_cast<uint2*>(g_hmid + rowoff)[lane] = pk;
    }
  }
  __syncthreads();
  // Phase 2a: warp 0, one thread per row
  if (tid < 32){
    int row = tid;
    float mo = 0.f, num = 0.f, den = 0.f;
    #pragma unroll
    for (int l=0;l<25;++l){
      float4 p = s_prt[row*PADP+l];
      mo = fmaxf(mo, p.x); num += p.y; den += p.z;
    }
    mo = fmaxf(mo, 1e-6f);
    float ms = fmaxf(__powf(mo, 3.4f), 1e-6f);
    float ratio = __fdividef(mo, ms);
    float cen = __fdividef(num, fmaxf(den, 1e-6f));  // ratio cancels in quotient
    s_r[row] = ratio;
    g_ratio[t*32+row] = ratio;
    float cs = wsum(cen);
    if (row == 0) g_cmean[t] = cs * (1.f/32.f);
  }
  __syncthreads();
  // Phase 2b: hmean[k] = sum_b ratio_b * sf[b][k] / 32
  if (tid < NH){
    float sum = 0.f;
    #pragma unroll
    for (int b=0;b<32;++b) sum = fmaf(s_r[b], s_sf[b*PADK+tid], sum);
    g_hmean[t*NH+tid] = sum * (1.f/32.f);
  }
}

// ---- K2: fb affine scan + clock prefix sum (512 thr x 8 elems, double) ----
__global__ void k_scan(){
  __shared__ double s_clk[TT];
  __shared__ double s_wa[16], s_wb[16], s_ws[16];
  int tid = threadIdx.x;
  int lane = tid & 31, warp = tid >> 5;
  int base = tid * 8;
  const double RATE_K = 0.725 * 6.283185307179586 * 0.004;
  const double TWOPI  = 6.283185307179586;
  const double INV2PI = 0.15915494309189535;
  double v = 0.0;
  #pragma unroll
  for (int j=0;j<8;++j){
    double u = 0.1*(((double)g_cmean[base+j] - 30.0)/40.0);
    v = 0.9*v + u;
  }
  double a = 0.43046721;  // 0.9^8
  double b = v;
  #pragma unroll
  for (int d=1; d<32; d<<=1){
    double pa = __shfl_up_sync(0xffffffffu, a, d);
    double pb = __shfl_up_sync(0xffffffffu, b, d);
    if (lane >= d){ b = a*pb + b; a = a*pa; }
  }
  if (lane == 31){ s_wa[warp]=a; s_wb[warp]=b; }
  __syncthreads();
  double wpre = 0.0;
  for (int w=0; w<warp; ++w) wpre = s_wa[w]*wpre + s_wb[w];
  double ae = __shfl_up_sync(0xffffffffu, a, 1);
  double be = __shfl_up_sync(0xffffffffu, b, 1);
  double fb = (lane==0) ? wpre : (ae*wpre + be);
  double csum = 0.0;
  #pragma unroll
  for (int j=0;j<8;++j){
    double u = 0.1*(((double)g_cmean[base+j] - 30.0)/40.0);
    fb = 0.9*fb + u;
    csum += RATE_K * (1.0 + 0.4*fb);
    s_clk[base+j] = csum;
  }
  double S = csum, ss = S;
  #pragma unroll
  for (int d=1; d<32; d<<=1){
    double p = __shfl_up_sync(0xffffffffu, ss, d);
    if (lane >= d) ss += p;
  }
  if (lane == 31) s_ws[warp] = ss;
  __syncthreads();
  double off = 0.0;
  for (int w=0; w<warp; ++w) off += s_ws[w];
  double excl = off + ss - S;
  #pragma unroll
  for (int j=0;j<8;++j){
    double x = excl + s_clk[base+j];
    double c = x - floor(x*INV2PI)*TWOPI;   // == fmod(x,2pi) for x>0
    g_sreso[base+j] = 0.4f * fast_sin((float)c);
  }
}

// ---- K3: h epilogue (blocks [0,TT)) + noise stream (blocks >= TT) ---------
__global__ __launch_bounds__(256) void k_out(const float4* __restrict__ nin,
                                             float4* __restrict__ outh,
                                             float4* __restrict__ outn){
  int bid = blockIdx.x;
  int tid = threadIdx.x;
  if (bid >= TT){
    const int NVN = BB*TT*NM/4;
    int idx = (bid - TT)*256 + tid;
    int stride = (gridDim.x - TT)*256;
    for (int j = idx; j < NVN; j += stride){
      int fi = j % (TT*NM/4);
      float4 v = nin[j];
      float4 f = reinterpret_cast<const float4*>(g_nfac)[fi];
      v.x *= f.x; v.y *= f.y; v.z *= f.z; v.w *= f.w;
      outn[j] = v;
    }
    return;
  }
  int t = bid;
  __shared__ float4 s_a[25], s_c[25];
  __shared__ float  s_r2[32];
  if (tid < 32) s_r2[tid] = g_ratio[t*32+tid];
  if (tid < 25){
    float sr = g_sreso[t];
    int k4 = tid*4;
    float4 rel;
    rel.x = (float)k4/99.0f*2.0f - 1.0f;
    rel.y = (float)(k4+1)/99.0f*2.0f - 1.0f;
    rel.z = (float)(k4+2)/99.0f*2.0f - 1.0f;
    rel.w = (float)(k4+3)/99.0f*2.0f - 1.0f;
    float scale = (t==0) ? 1.0f : 0.6f;
    float4 a;
    a.x = scale*(1.0f + sr*rel.x); a.y = scale*(1.0f + sr*rel.y);
    a.z = scale*(1.0f + sr*rel.z); a.w = scale*(1.0f + sr*rel.w);
    float4 c = make_float4(0.f,0.f,0.f,0.f);
    if (t >= 149){
      float srp = g_sreso[t-149];
      float4 hm = reinterpret_cast<const float4*>(g_hmean)[(t-149)*25 + tid];
      c.x = 0.4f*(1.0f + srp*rel.x)*hm.x;
      c.y = 0.4f*(1.0f + srp*rel.y)*hm.y;
      c.z = 0.4f*(1.0f + srp*rel.z)*hm.z;
      c.w = 0.4f*(1.0f + srp*rel.w)*hm.w;
    }
    s_a[tid] = a; s_c[tid] = c;
  }
  __syncthreads();
  for (int q = tid; q < 800; q += 256){
    int row = q / 25;
    int kq  = q - row*25;
    float r = s_r2[row];
    size_t half_off = ((size_t)row*TT + t)*NH;
    uint2 pk = reinterpret_cast<const uint2*>(g_hmid + half_off)[kq];
    __half2 p0 = *reinterpret_cast<__half2*>(&pk.x);
    __half2 p1 = *reinterpret_cast<__half2*>(&pk.y);
    float2 v01 = __half22float2(p0);
    float2 v23 = __half22float2(p1);
    float4 a = s_a[kq], c = s_c[kq];
    float4 o;
    o.x = fmaf(a.x, r*v01.x, c.x); o.y = fmaf(a.y, r*v01.y, c.y);
    o.z = fmaf(a.z, r*v23.x, c.z); o.w = fmaf(a.w, r*v23.y, c.w);
    size_t idx = ((size_t)row*TT + t)*25 + kq;
    outh[idx] = o;
  }
}

extern "C" void kernel_launch(void* const* d_in, const int* in_sizes, int n_in,
                              void* d_out, int out_size){
  const float* harm  = (const float*)d_in[0];
  const float* noise = (const float*)d_in[1];
  float* outh = (float*)d_out;
  float* outn = outh + (size_t)BB*TT*NH;
  k_stats<<<TT, 512>>>(harm);
  k_scan <<<1, 512>>>();
  k_out  <<<TT + 2048, 256>>>((const float4*)noise, (float4*)outh, (float4*)outn);
}

// round 16
// speedup vs baseline: 1.6251x; 1.2502x over previous
#include <cuda_runtime.h>
#include <cuda_fp16.h>
#include <math.h>

#define TT 4096
#define BB 32
#define NH 100
#define NM 65
#define PADK 104   // float stride for sf rows
#define PADR 27    // float stride for scalar partials

// ---- scratch (__device__ globals: allocations forbidden) ----
__device__ __align__(16) float  g_nfac[TT*NM];
__device__ __align__(16) __half g_hmid[(size_t)BB*TT*NH];   // 26.2MB fp16 (sf, ratio deferred)
__device__ __align__(16) float  g_hmean[TT*NH];
__device__ float g_ratio[TT*BB];
__device__ float g_cmean[TT];
__device__ float g_sreso[TT];

__device__ __forceinline__ float wsum(float v){
  #pragma unroll
  for (int d=16; d; d>>=1) v += __shfl_xor_sync(0xffffffffu, v, d);
  return v;
}
// reduce to [-pi,pi] then MUFU sin; error ~1e-5 rad at |arg|<=600
__device__ __forceinline__ float fast_sin(float arg){
  float n = floorf(fmaf(arg, 0.15915494309f, 0.5f));
  float a = fmaf(n, -6.28318530718f, arg);
  return __sinf(a);
}

// ---- K1: per-t block. Phase1: pow+scalar partials. Phase2: reduce. --------
// (512,4) launch bounds pin regs<=32 so 4 blocks/SM — the R13-measured config.
__global__ __launch_bounds__(512, 4) void k_stats(const float* __restrict__ harm){
  int t = blockIdx.x;
  int warp = threadIdx.x>>5, lane = threadIdx.x&31;
  int tid = threadIdx.x;
  __shared__ float s_tfac[NH];
  __shared__ float s_sf[32*PADK];
  __shared__ float s_max[32*PADR];
  __shared__ float s_num[32*PADR];
  __shared__ float s_den[32*PADR];
  __shared__ float s_r[32];
  if (tid < NH+NM){
    // f32 phase recurrence tracked by double closed form (~1e-5 rad / 4096)
    const double INC  = (double)(float)1.0053096491487339;  // f32(2pi*40*64/16000)
    const double WRAP = (double)(float)6.283185307179586;   // f32(2pi)
    float phase = (float)fmod((double)(t+1)*INC, WRAP);
    if (tid < NH){
      float off = (float)((double)tid * (4.71238898038469/99.0));
      s_tfac[tid] = 1.0f + 0.225f*fast_sin(phase + off);
    } else {
      int m = tid - NH;
      float rb = (float)m * 7.853981633974483f;             // f32(2.5pi)*m
      g_nfac[t*NM+m] = 1.0f + 0.6f*fast_sin(rb + phase);
    }
  }
  __syncthreads();
  bool act = lane < 25;
  float4 f = act ? reinterpret_cast<const float4*>(s_tfac)[lane]
                 : make_float4(0.f,0.f,0.f,0.f);
  float k0 = (float)(lane*4);
  #pragma unroll
  for (int r=0;r<2;++r){
    int b = warp + r*16;                      // row 0..31
    size_t rowoff = ((size_t)b*TT + t)*NH;
    float4 x = act ? reinterpret_cast<const float4*>(harm + rowoff)[lane]
                   : make_float4(0.f,0.f,0.f,0.f);
    // pow without clamp: x>=0; x<1e-6 diff <= 9e-21 abs (negligible)
    float4 sf;
    sf.x = __powf(x.x, 3.4f)*f.x;
    sf.y = __powf(x.y, 3.4f)*f.y;
    sf.z = __powf(x.z, 3.4f)*f.z;
    sf.w = __powf(x.w, 3.4f)*f.w;
    float lmax = fmaxf(fmaxf(x.x,x.y), fmaxf(x.z,x.w));
    float num = sf.x*k0 + sf.y*(k0+1.f) + sf.z*(k0+2.f) + sf.w*(k0+3.f);
    float den = sf.x+sf.y+sf.z+sf.w;
    if (act){
      reinterpret_cast<float4*>(s_sf + b*PADK)[lane] = sf;
      s_max[b*PADR+lane] = lmax;
      s_num[b*PADR+lane] = num;
      s_den[b*PADR+lane] = den;
      __half2 p0 = __floats2half2_rn(sf.x, sf.y);
      __half2 p1 = __floats2half2_rn(sf.z, sf.w);
      uint2 pk;
      pk.x = *reinterpret_cast<unsigned int*>(&p0);
      pk.y = *reinterpret_cast<unsigned int*>(&p1);
      reinterpret_cast<uint2*>(g_hmid + rowoff)[lane] = pk;
    }
  }
  __syncthreads();
  // Phase 2a: warp 0, one thread per row
  if (tid < 32){
    int row = tid;
    float mo = 0.f, num = 0.f, den = 0.f;
    #pragma unroll
    for (int l=0;l<25;++l){
      mo  = fmaxf(mo, s_max[row*PADR+l]);
      num += s_num[row*PADR+l];
      den += s_den[row*PADR+l];
    }
    mo = fmaxf(mo, 1e-6f);
    float ms = fmaxf(__powf(mo, 3.4f), 1e-6f);
    float ratio = __fdividef(mo, ms);
    float cen = __fdividef(num, fmaxf(den, 1e-6f));  // ratio cancels in quotient
    s_r[row] = ratio;
    g_ratio[t*32+row] = ratio;
    float cs = wsum(cen);
    if (row == 0) g_cmean[t] = cs * (1.f/32.f);
  }
  __syncthreads();
  // Phase 2b: hmean[k] = sum_b ratio_b * sf[b][k] / 32
  if (tid < NH){
    float sum = 0.f;
    #pragma unroll
    for (int b=0;b<32;++b) sum = fmaf(s_r[b], s_sf[b*PADK+tid], sum);
    g_hmean[t*NH+tid] = sum * (1.f/32.f);
  }
}

// ---- K2: fb affine scan + clock prefix sum (512 thr x 8 elems, double) ----
__global__ void k_scan(){
  __shared__ double s_clk[TT];
  __shared__ double s_wa[16], s_wb[16], s_ws[16];
  int tid = threadIdx.x;
  int lane = tid & 31, warp = tid >> 5;
  int base = tid * 8;
  const double RATE_K = 0.725 * 6.283185307179586 * 0.004;
  const double TWOPI  = 6.283185307179586;
  const double INV2PI = 0.15915494309189535;
  double v = 0.0;
  #pragma unroll
  for (int j=0;j<8;++j){
    double u = 0.1*(((double)g_cmean[base+j] - 30.0)/40.0);
    v = 0.9*v + u;
  }
  double a = 0.43046721;  // 0.9^8
  double b = v;
  #pragma unroll
  for (int d=1; d<32; d<<=1){
    double pa = __shfl_up_sync(0xffffffffu, a, d);
    double pb = __shfl_up_sync(0xffffffffu, b, d);
    if (lane >= d){ b = a*pb + b; a = a*pa; }
  }
  if (lane == 31){ s_wa[warp]=a; s_wb[warp]=b; }
  __syncthreads();
  double wpre = 0.0;
  for (int w=0; w<warp; ++w) wpre = s_wa[w]*wpre + s_wb[w];
  double ae = __shfl_up_sync(0xffffffffu, a, 1);
  double be = __shfl_up_sync(0xffffffffu, b, 1);
  double fb = (lane==0) ? wpre : (ae*wpre + be);
  double csum = 0.0;
  #pragma unroll
  for (int j=0;j<8;++j){
    double u = 0.1*(((double)g_cmean[base+j] - 30.0)/40.0);
    fb = 0.9*fb + u;
    csum += RATE_K * (1.0 + 0.4*fb);
    s_clk[base+j] = csum;
  }
  double S = csum, ss = S;
  #pragma unroll
  for (int d=1; d<32; d<<=1){
    double p = __shfl_up_sync(0xffffffffu, ss, d);
    if (lane >= d) ss += p;
  }
  if (lane == 31) s_ws[warp] = ss;
  __syncthreads();
  double off = 0.0;
  for (int w=0; w<warp; ++w) off += s_ws[w];
  double excl = off + ss - S;
  #pragma unroll
  for (int j=0;j<8;++j){
    double x = excl + s_clk[base+j];
    double c = x - floor(x*INV2PI)*TWOPI;   // == fmod(x,2pi) for x>0
    g_sreso[base+j] = 0.4f * fast_sin((float)c);
  }
}

// ---- K3: h epilogue (blocks [0,TT)) + noise stream (blocks >= TT) ---------
__global__ __launch_bounds__(256) void k_out(const float4* __restrict__ nin,
                                             float4* __restrict__ outh,
                                             float4* __restrict__ outn){
  int bid = blockIdx.x;
  int tid = threadIdx.x;
  if (bid >= TT){
    const int NVN = BB*TT*NM/4;
    int idx = (bid - TT)*256 + tid;
    int stride = (gridDim.x - TT)*256;
    for (int j = idx; j < NVN; j += stride){
      int fi = j % (TT*NM/4);
      float4 v = nin[j];
      float4 f = reinterpret_cast<const float4*>(g_nfac)[fi];
      v.x *= f.x; v.y *= f.y; v.z *= f.z; v.w *= f.w;
      outn[j] = v;
    }
    return;
  }
  int t = bid;
  __shared__ float4 s_a[25], s_c[25];
  __shared__ float  s_r2[32];
  if (tid < 32) s_r2[tid] = g_ratio[t*32+tid];
  if (tid < 25){
    float sr = g_sreso[t];
    int k4 = tid*4;
    float4 rel;
    rel.x = (float)k4/99.0f*2.0f - 1.0f;
    rel.y = (float)(k4+1)/99.0f*2.0f - 1.0f;
    rel.z = (float)(k4+2)/99.0f*2.0f - 1.0f;
    rel.w = (float)(k4+3)/99.0f*2.0f - 1.0f;
    float scale = (t==0) ? 1.0f : 0.6f;
    float4 a;
    a.x = scale*(1.0f + sr*rel.x); a.y = scale*(1.0f + sr*rel.y);
    a.z = scale*(1.0f + sr*rel.z); a.w = scale*(1.0f + sr*rel.w);
    float4 c = make_float4(0.f,0.f,0.f,0.f);
    if (t >= 149){
      float srp = g_sreso[t-149];
      float4 hm = reinterpret_cast<const float4*>(g_hmean)[(t-149)*25 + tid];
      c.x = 0.4f*(1.0f + srp*rel.x)*hm.x;
      c.y = 0.4f*(1.0f + srp*rel.y)*hm.y;
      c.z = 0.4f*(1.0f + srp*rel.z)*hm.z;
      c.w = 0.4f*(1.0f + srp*rel.w)*hm.w;
    }
    s_a[tid] = a; s_c[tid] = c;
  }
  __syncthreads();
  for (int q = tid; q < 800; q += 256){
    int row = q / 25;
    int kq  = q - row*25;
    float r = s_r2[row];
    size_t half_off = ((size_t)row*TT + t)*NH;
    uint2 pk = reinterpret_cast<const uint2*>(g_hmid + half_off)[kq];
    __half2 p0 = *reinterpret_cast<__half2*>(&pk.x);
    __half2 p1 = *reinterpret_cast<__half2*>(&pk.y);
    float2 v01 = __half22float2(p0);
    float2 v23 = __half22float2(p1);
    float4 a = s_a[kq], c = s_c[kq];
    float4 o;
    o.x = fmaf(a.x, r*v01.x, c.x); o.y = fmaf(a.y, r*v01.y, c.y);
    o.z = fmaf(a.z, r*v23.x, c.z); o.w = fmaf(a.w, r*v23.y, c.w);
    size_t idx = ((size_t)row*TT + t)*25 + kq;
    outh[idx] = o;
  }
}

extern "C" void kernel_launch(void* const* d_in, const int* in_sizes, int n_in,
                              void* d_out, int out_size){
  const float* harm  = (const float*)d_in[0];
  const float* noise = (const float*)d_in[1];
  float* outh = (float*)d_out;
  float* outn = outh + (size_t)BB*TT*NH;
  k_stats<<<TT, 512>>>(harm);
  k_scan <<<1, 512>>>();
  k_out  <<<TT + 2048, 256>>>((const float4*)noise, (float4*)outh, (float4*)outn);
}